// round 3
// baseline (speedup 1.0000x reference)
#include <cuda_runtime.h>
#include <math.h>

#define NB 128
#define DD 192
#define DEPTHL 12
#define NHD 3
#define HDIM 64
#define NE 4
#define NT 65
#define NTP 66
#define NCLS 100
#define DH 384
#define NTHR 384
#define NWARP 12
#define CK 36            // MoE chunk rows (3 rowgroups x 12)

typedef unsigned long long ull;

struct __align__(16) SM {
    float t[NTP * DD];
    float Y[NTP * DD];
    float S[NTP * DH];     // qkv(66x192) + O(66x192); MoE: Yc(36x192) then Hc(36x384)
    float m[NTP];
    float rs[NTP];
    float gl[NTP * NE];
    float selw[NTP * 2];
    float ewt[NE * 72];
    int   seli[NTP * 2];
    int   elist[NE * 72];
    int   ecnt[NE];
};

__device__ __forceinline__ ull fma2(ull a, ull b, ull c) {
    ull d;
    asm("fma.rn.f32x2 %0, %1, %2, %3;" : "=l"(d) : "l"(a), "l"(b), "l"(c));
    return d;
}
__device__ __forceinline__ float f2sum(ull v) {
    float lo = __uint_as_float((unsigned)(v & 0xffffffffull));
    float hi = __uint_as_float((unsigned)(v >> 32));
    return lo + hi;
}

__device__ __forceinline__ float gelu_exact(float x) {
    return 0.5f * x * (1.0f + erff(x * 0.70710678118654752f));
}

__device__ __forceinline__ float dot4(float4 a, float4 b) {
    return a.x * b.x + a.y * b.y + a.z * b.z + a.w * b.w;
}

__device__ __forceinline__ void ln_stats(const float* __restrict__ base, int n0, int n1,
                                         float* __restrict__ m, float* __restrict__ rs) {
    int warp = threadIdx.x >> 5, lane = threadIdx.x & 31;
    for (int n = n0 + warp; n < n1; n += NWARP) {
        const float* row = base + n * DD;
        float s = 0.f;
        for (int c = lane; c < DD; c += 32) s += row[c];
#pragma unroll
        for (int o = 16; o; o >>= 1) s += __shfl_xor_sync(0xffffffffu, s, o);
        float mm = s * (1.0f / DD);
        float q = 0.f;
        for (int c = lane; c < DD; c += 32) { float d = row[c] - mm; q += d * d; }
#pragma unroll
        for (int o = 16; o; o >>= 1) q += __shfl_xor_sync(0xffffffffu, q, o);
        if (lane == 0) { m[n] = mm; rs[n] = rsqrtf(q * (1.0f / DD) + 1e-5f); }
    }
}

__global__ void __launch_bounds__(NTHR, 1) hypervit_kernel(
    const float* __restrict__ x, const float* __restrict__ conv_w, const float* __restrict__ conv_b,
    const float* __restrict__ pe_g, const float* __restrict__ pe_b,
    const float* __restrict__ cls_token, const float* __restrict__ pos_embed,
    const float* __restrict__ n1_g, const float* __restrict__ n1_b,
    const float* __restrict__ qkv_w, const float* __restrict__ temp,
    const float* __restrict__ proj_w, const float* __restrict__ proj_b,
    const float* __restrict__ n2_g, const float* __restrict__ n2_b,
    const float* __restrict__ gate_w, const float* __restrict__ gate_b,
    const float* __restrict__ e_w1, const float* __restrict__ e_b1,
    const float* __restrict__ e_w2, const float* __restrict__ e_b2,
    const float* __restrict__ attn_scale, const float* __restrict__ mlp_scale,
    const float* __restrict__ norm_g, const float* __restrict__ norm_b,
    const float* __restrict__ hc_w, const float* __restrict__ hc_b,
    const float* __restrict__ head_w, const float* __restrict__ head_b,
    float* __restrict__ out)
{
    extern __shared__ char smraw[];
    SM* sp = (SM*)smraw;
    const int b = blockIdx.x;
    const int tid = threadIdx.x;
    const int warp = tid >> 5, lane = tid & 31;
    float* t = sp->t;
    float* Y = sp->Y;
    float* S = sp->S;
    float* O = S + NTP * DD;

    for (int i = tid; i < NTP * DH; i += NTHR) S[i] = 0.f;

    // ======================= patch embed =======================
    {
        float* P = Y;  // 64 x 48
        for (int i = tid; i < 64 * 48; i += NTHR) {
            int patch = i / 48, f = i % 48;
            int c = f >> 4, pi = (f >> 2) & 3, pj = f & 3;
            int ph = patch >> 3, pw = patch & 7;
            P[i] = x[((b * 3 + c) * 32 + ph * 4 + pi) * 32 + pw * 4 + pj];
        }
        __syncthreads();
        for (int task = tid; task < 64 * DD; task += NTHR) {
            int p = task / DD, c = task % DD;
            const float* w = conv_w + c * 48;
            float acc = conv_b[c];
#pragma unroll
            for (int k = 0; k < 48; k += 4) {
                float4 w4 = *(const float4*)(w + k);
                float4 p4 = *(const float4*)(P + p * 48 + k);
                acc += dot4(p4, w4);
            }
            t[(p + 1) * DD + c] = acc;
        }
        __syncthreads();
        ln_stats(t, 1, 65, sp->m, sp->rs);
        __syncthreads();
        for (int i = tid; i < 64 * DD; i += NTHR) {
            int n = 1 + i / DD, c = i % DD;
            t[n * DD + c] = (t[n * DD + c] - sp->m[n]) * sp->rs[n] * pe_g[c] + pe_b[c]
                            + pos_embed[n * DD + c];
        }
        for (int c = tid; c < DD; c += NTHR) {
            t[c] = cls_token[c] + pos_embed[c];
            t[65 * DD + c] = 0.f;
        }
    }
    __syncthreads();

    // ======================= transformer layers =======================
    for (int l = 0; l < DEPTHL; l++) {
        // ---- LN1 -> Y ----
        ln_stats(t, 0, 65, sp->m, sp->rs);
        __syncthreads();
        for (int i = tid; i < 65 * DD; i += NTHR) {
            int n = i / DD, c = i % DD;
            Y[i] = (t[i] - sp->m[n]) * sp->rs[n] * n1_g[l * DD + c] + n1_b[l * DD + c];
        }
        for (int c = tid; c < DD; c += NTHR) Y[65 * DD + c] = 0.f;
        __syncthreads();

        const float asc = attn_scale[l];
        const int ct = tid & 63, rg = tid >> 6;      // 64 col-threads x 6 rowgroups

        // ---- attention, per head ----
        for (int h = 0; h < NHD; h++) {
            // qkv GEMM: thread owns q[ct], k[ct], v[ct]; rows rg*11 .. rg*11+10
            {
                const ulonglong2* wq = (const ulonglong2*)(qkv_w + ((size_t)(l * 3 + 0) * DD + h * HDIM + ct) * DD);
                const ulonglong2* wk = (const ulonglong2*)(qkv_w + ((size_t)(l * 3 + 1) * DD + h * HDIM + ct) * DD);
                const ulonglong2* wvp = (const ulonglong2*)(qkv_w + ((size_t)(l * 3 + 2) * DD + h * HDIM + ct) * DD);
                ull aq[11], ak[11], av[11];
#pragma unroll
                for (int r = 0; r < 11; r++) { aq[r] = 0; ak[r] = 0; av[r] = 0; }
                ulonglong2 cq = wq[0], ck = wk[0], cv = wvp[0];
                const char* ybase = (const char*)(Y + (rg * 11) * DD);
                for (int kk = 0; kk < 48; kk++) {
                    ulonglong2 nq, nk, nv;
                    if (kk < 47) { nq = wq[kk + 1]; nk = wk[kk + 1]; nv = wvp[kk + 1]; }
                    const char* yb = ybase + kk * 16;
#pragma unroll
                    for (int r = 0; r < 11; r++) {
                        ulonglong2 yv = *(const ulonglong2*)(yb + r * (DD * 4));
                        aq[r] = fma2(yv.x, cq.x, aq[r]); aq[r] = fma2(yv.y, cq.y, aq[r]);
                        ak[r] = fma2(yv.x, ck.x, ak[r]); ak[r] = fma2(yv.y, ck.y, ak[r]);
                        av[r] = fma2(yv.x, cv.x, av[r]); av[r] = fma2(yv.y, cv.y, av[r]);
                    }
                    cq = nq; ck = nk; cv = nv;
                }
#pragma unroll
                for (int r = 0; r < 11; r++) {
                    int row = rg * 11 + r;
                    S[row * DD + ct]       = f2sum(aq[r]);
                    S[row * DD + 64 + ct]  = f2sum(ak[r]);
                    S[row * DD + 128 + ct] = f2sum(av[r]);
                }
            }
            __syncthreads();

            // banded attention (|i-j| <= 3)
            {
                float coef = 0.125f / temp[l * NHD + h];
                for (int i = warp; i < 65; i += NWARP) {
                    int jlo = (i - 3 < 0) ? 0 : i - 3;
                    int jhi = (i + 3 > 64) ? 64 : i + 3;
                    int cnt = jhi - jlo + 1;
                    const float* q = S + i * DD;
                    float2 qv = *(const float2*)(q + 2 * lane);
                    float sc[7];
#pragma unroll
                    for (int jj = 0; jj < 7; jj++) {
                        if (jj < cnt) {
                            const float* k = S + (jlo + jj) * DD + 64;
                            float2 kv = *(const float2*)(k + 2 * lane);
                            float p = qv.x * kv.x + qv.y * kv.y;
#pragma unroll
                            for (int o = 16; o; o >>= 1) p += __shfl_xor_sync(0xffffffffu, p, o);
                            sc[jj] = p * coef;
                        }
                    }
                    float mx = sc[0];
#pragma unroll
                    for (int jj = 1; jj < 7; jj++) if (jj < cnt) mx = fmaxf(mx, sc[jj]);
                    float ssum = 0.f;
#pragma unroll
                    for (int jj = 0; jj < 7; jj++) if (jj < cnt) { sc[jj] = expf(sc[jj] - mx); ssum += sc[jj]; }
                    float inv = 1.0f / ssum;
                    float o0 = 0.f, o1 = 0.f;
#pragma unroll
                    for (int jj = 0; jj < 7; jj++) {
                        if (jj < cnt) {
                            const float* v = S + (jlo + jj) * DD + 128;
                            float2 vv = *(const float2*)(v + 2 * lane);
                            o0 += sc[jj] * vv.x;
                            o1 += sc[jj] * vv.y;
                        }
                    }
                    O[i * DD + h * HDIM + 2 * lane]     = o0 * inv;
                    O[i * DD + h * HDIM + 2 * lane + 1] = o1 * inv;
                }
            }
            __syncthreads();
        }

        // ---- proj + residual (cols ct, ct+64, ct+128; rows rg*11..+10) ----
        {
            const ulonglong2* w0 = (const ulonglong2*)(proj_w + ((size_t)l * DD + ct) * DD);
            const ulonglong2* w1 = (const ulonglong2*)(proj_w + ((size_t)l * DD + 64 + ct) * DD);
            const ulonglong2* w2 = (const ulonglong2*)(proj_w + ((size_t)l * DD + 128 + ct) * DD);
            float pb0 = proj_b[l * DD + ct], pb1 = proj_b[l * DD + 64 + ct], pb2 = proj_b[l * DD + 128 + ct];
            ull a0[11], a1[11], a2[11];
#pragma unroll
            for (int r = 0; r < 11; r++) { a0[r] = 0; a1[r] = 0; a2[r] = 0; }
            ulonglong2 c0 = w0[0], c1 = w1[0], c2 = w2[0];
            const char* obase = (const char*)(O + (rg * 11) * DD);
            for (int kk = 0; kk < 48; kk++) {
                ulonglong2 n0, n1, n2;
                if (kk < 47) { n0 = w0[kk + 1]; n1 = w1[kk + 1]; n2 = w2[kk + 1]; }
                const char* ob = obase + kk * 16;
#pragma unroll
                for (int r = 0; r < 11; r++) {
                    ulonglong2 ov = *(const ulonglong2*)(ob + r * (DD * 4));
                    a0[r] = fma2(ov.x, c0.x, a0[r]); a0[r] = fma2(ov.y, c0.y, a0[r]);
                    a1[r] = fma2(ov.x, c1.x, a1[r]); a1[r] = fma2(ov.y, c1.y, a1[r]);
                    a2[r] = fma2(ov.x, c2.x, a2[r]); a2[r] = fma2(ov.y, c2.y, a2[r]);
                }
                c0 = n0; c1 = n1; c2 = n2;
            }
#pragma unroll
            for (int r = 0; r < 11; r++) {
                int row = rg * 11 + r;
                t[row * DD + ct]       += asc * (f2sum(a0[r]) + pb0);
                t[row * DD + 64 + ct]  += asc * (f2sum(a1[r]) + pb1);
                t[row * DD + 128 + ct] += asc * (f2sum(a2[r]) + pb2);
            }
        }
        __syncthreads();

        // ---- LN2 -> Y ----
        ln_stats(t, 0, 65, sp->m, sp->rs);
        __syncthreads();
        for (int i = tid; i < 65 * DD; i += NTHR) {
            int n = i / DD, c = i % DD;
            Y[i] = (t[i] - sp->m[n]) * sp->rs[n] * n2_g[l * DD + c] + n2_b[l * DD + c];
        }
        for (int c = tid; c < DD; c += NTHR) Y[65 * DD + c] = 0.f;
        __syncthreads();

        // ---- gating ----
        for (int task = tid; task < NT * NE; task += NTHR) {
            int n = task >> 2, e = task & 3;
            const float* gw = gate_w + ((size_t)l * NE + e) * DD;
            float acc = gate_b[l * NE + e];
            for (int c = 0; c < DD; c += 4) {
                float4 y4 = *(const float4*)(Y + n * DD + c);
                float4 w4 = *(const float4*)(gw + c);
                acc += dot4(y4, w4);
            }
            sp->gl[n * NE + e] = acc;
        }
        __syncthreads();
        if (tid < NT) {
            float vv[4] = { sp->gl[tid * 4 + 0], sp->gl[tid * 4 + 1],
                            sp->gl[tid * 4 + 2], sp->gl[tid * 4 + 3] };
            int i0 = 0; float bmax = vv[0];
#pragma unroll
            for (int e = 1; e < 4; e++) if (vv[e] > bmax) { bmax = vv[e]; i0 = e; }
            int i1 = -1; float b2v = -1e30f;
#pragma unroll
            for (int e = 0; e < 4; e++) if (e != i0 && vv[e] > b2v) { b2v = vv[e]; i1 = e; }
            float w1 = expf(b2v - bmax);
            float inv = 1.0f / (1.0f + w1);
            sp->seli[tid * 2 + 0] = i0;
            sp->seli[tid * 2 + 1] = i1;
            sp->selw[tid * 2 + 0] = inv;
            sp->selw[tid * 2 + 1] = w1 * inv;
        }
        __syncthreads();
        if (tid == 0) {
            float msc = mlp_scale[l];
            int cnt[4] = { 0, 0, 0, 0 };
            for (int n = 0; n < NT; n++) {
                for (int sidx = 0; sidx < 2; sidx++) {
                    int e = sp->seli[n * 2 + sidx];
                    sp->elist[e * 72 + cnt[e]] = n;
                    sp->ewt[e * 72 + cnt[e]] = sp->selw[n * 2 + sidx] * msc;
                    cnt[e]++;
                }
            }
            for (int e = 0; e < 4; e++) {
                while (cnt[e] % CK != 0) {
                    sp->elist[e * 72 + cnt[e]] = 65;   // zero row
                    sp->ewt[e * 72 + cnt[e]] = 0.f;
                    cnt[e]++;
                }
                sp->ecnt[e] = cnt[e];
            }
        }
        __syncthreads();

        // ---- expert FFNs (token-grouped, 36-row chunks) ----
        float* Yc = S;             // 36 x DD
        float* Hc = S + CK * DD;   // 36 x DH
        for (int e = 0; e < NE; e++) {
            int cnt = sp->ecnt[e];
            int nch = cnt / CK;
            for (int ch = 0; ch < nch; ch++) {
                for (int i = tid; i < CK * DD; i += NTHR) {
                    int r = i / DD, c = i % DD;
                    int tok = sp->elist[e * 72 + ch * CK + r];
                    Yc[i] = Y[tok * DD + c];
                }
                __syncthreads();
                // GEMM1: 36 x 384 = Yc @ w1^T, gelu.  128 colthreads x 3 rowgroups x 12 rows
                {
                    int ct2 = tid & 127, rg2 = tid >> 7;
                    const ulonglong2* w0 = (const ulonglong2*)(e_w1 + ((size_t)(l * NE + e) * DH + ct2) * DD);
                    const ulonglong2* w1 = (const ulonglong2*)(e_w1 + ((size_t)(l * NE + e) * DH + 128 + ct2) * DD);
                    const ulonglong2* w2 = (const ulonglong2*)(e_w1 + ((size_t)(l * NE + e) * DH + 256 + ct2) * DD);
                    float b0 = e_b1[(size_t)(l * NE + e) * DH + ct2];
                    float b1 = e_b1[(size_t)(l * NE + e) * DH + 128 + ct2];
                    float b2 = e_b1[(size_t)(l * NE + e) * DH + 256 + ct2];
                    ull a0[12], a1[12], a2[12];
#pragma unroll
                    for (int r = 0; r < 12; r++) { a0[r] = 0; a1[r] = 0; a2[r] = 0; }
                    ulonglong2 c0 = w0[0], c1 = w1[0], c2 = w2[0];
                    const char* ybase = (const char*)(Yc + (rg2 * 12) * DD);
                    for (int kk = 0; kk < 48; kk++) {
                        ulonglong2 n0, n1, n2;
                        if (kk < 47) { n0 = w0[kk + 1]; n1 = w1[kk + 1]; n2 = w2[kk + 1]; }
                        const char* yb = ybase + kk * 16;
#pragma unroll
                        for (int r = 0; r < 12; r++) {
                            ulonglong2 yv = *(const ulonglong2*)(yb + r * (DD * 4));
                            a0[r] = fma2(yv.x, c0.x, a0[r]); a0[r] = fma2(yv.y, c0.y, a0[r]);
                            a1[r] = fma2(yv.x, c1.x, a1[r]); a1[r] = fma2(yv.y, c1.y, a1[r]);
                            a2[r] = fma2(yv.x, c2.x, a2[r]); a2[r] = fma2(yv.y, c2.y, a2[r]);
                        }
                        c0 = n0; c1 = n1; c2 = n2;
                    }
#pragma unroll
                    for (int r = 0; r < 12; r++) {
                        int row = rg2 * 12 + r;
                        Hc[row * DH + ct2]       = gelu_exact(f2sum(a0[r]) + b0);
                        Hc[row * DH + 128 + ct2] = gelu_exact(f2sum(a1[r]) + b1);
                        Hc[row * DH + 256 + ct2] = gelu_exact(f2sum(a2[r]) + b2);
                    }
                }
                __syncthreads();
                // GEMM2: 36 x 192 = Hc @ w2^T, scatter += into t.  64 ct x 6 rg x 6 rows
                {
                    const ulonglong2* w0 = (const ulonglong2*)(e_w2 + ((size_t)(l * NE + e) * DD + ct) * DH);
                    const ulonglong2* w1 = (const ulonglong2*)(e_w2 + ((size_t)(l * NE + e) * DD + 64 + ct) * DH);
                    const ulonglong2* w2 = (const ulonglong2*)(e_w2 + ((size_t)(l * NE + e) * DD + 128 + ct) * DH);
                    float b0 = e_b2[(size_t)(l * NE + e) * DD + ct];
                    float b1 = e_b2[(size_t)(l * NE + e) * DD + 64 + ct];
                    float b2 = e_b2[(size_t)(l * NE + e) * DD + 128 + ct];
                    ull a0[6], a1[6], a2[6];
#pragma unroll
                    for (int r = 0; r < 6; r++) { a0[r] = 0; a1[r] = 0; a2[r] = 0; }
                    ulonglong2 c0 = w0[0], c1 = w1[0], c2 = w2[0];
                    const char* hbase = (const char*)(Hc + (rg * 6) * DH);
                    for (int kk = 0; kk < 96; kk++) {
                        ulonglong2 n0, n1, n2;
                        if (kk < 95) { n0 = w0[kk + 1]; n1 = w1[kk + 1]; n2 = w2[kk + 1]; }
                        const char* hb = hbase + kk * 16;
#pragma unroll
                        for (int r = 0; r < 6; r++) {
                            ulonglong2 hv = *(const ulonglong2*)(hb + r * (DH * 4));
                            a0[r] = fma2(hv.x, c0.x, a0[r]); a0[r] = fma2(hv.y, c0.y, a0[r]);
                            a1[r] = fma2(hv.x, c1.x, a1[r]); a1[r] = fma2(hv.y, c1.y, a1[r]);
                            a2[r] = fma2(hv.x, c2.x, a2[r]); a2[r] = fma2(hv.y, c2.y, a2[r]);
                        }
                        c0 = n0; c1 = n1; c2 = n2;
                    }
                    int idx0 = e * 72 + ch * CK + rg * 6;
#pragma unroll
                    for (int r = 0; r < 6; r++) {
                        int tok = sp->elist[idx0 + r];
                        float wt = sp->ewt[idx0 + r];
                        t[tok * DD + ct]       += wt * (f2sum(a0[r]) + b0);
                        t[tok * DD + 64 + ct]  += wt * (f2sum(a1[r]) + b1);
                        t[tok * DD + 128 + ct] += wt * (f2sum(a2[r]) + b2);
                    }
                }
                __syncthreads();
            }
        }
    }

    // ======================= final norm + circulant head =======================
    ln_stats(t, 0, 1, sp->m, sp->rs);
    __syncthreads();
    float* cls = Y;
    for (int c = tid; c < DD; c += NTHR)
        cls[c] = (t[c] - sp->m[0]) * sp->rs[0] * norm_g[c] + norm_b[c];
    __syncthreads();
    float* HH = S;
    for (int ko = tid; ko < 2 * DD; ko += NTHR) {
        int k = ko / 96, o = ko % 96;
        float acc = hc_b[ko];
#pragma unroll
        for (int j = 0; j < 4; j++) {
            const float* w = hc_w + ((size_t)((k - j) & 3) * 96 + o) * 48;
            const float* xv = cls + j * 48;
#pragma unroll
            for (int c = 0; c < 48; c += 4) {
                float4 w4 = *(const float4*)(w + c);
                float4 x4 = *(const float4*)(xv + c);
                acc += dot4(x4, w4);
            }
        }
        HH[ko] = gelu_exact(acc);
    }
    __syncthreads();
    for (int ci = tid; ci < NCLS; ci += NTHR) {
        const float* w = head_w + (size_t)ci * (2 * DD);
        float acc = head_b[ci];
        for (int c = 0; c < 2 * DD; c += 4) {
            float4 w4 = *(const float4*)(w + c);
            float4 h4 = *(const float4*)(HH + c);
            acc += dot4(h4, w4);
        }
        out[b * NCLS + ci] = acc;
    }
}

extern "C" void kernel_launch(void* const* d_in, const int* in_sizes, int n_in,
                              void* d_out, int out_size) {
    (void)in_sizes; (void)n_in; (void)out_size;
    const float* x          = (const float*)d_in[0];
    const float* conv_w     = (const float*)d_in[1];
    const float* conv_b     = (const float*)d_in[2];
    const float* pe_g       = (const float*)d_in[3];
    const float* pe_b       = (const float*)d_in[4];
    const float* cls_token  = (const float*)d_in[5];
    const float* pos_embed  = (const float*)d_in[6];
    const float* n1_g       = (const float*)d_in[7];
    const float* n1_b       = (const float*)d_in[8];
    const float* qkv_w      = (const float*)d_in[9];
    const float* temp       = (const float*)d_in[10];
    const float* proj_w     = (const float*)d_in[11];
    const float* proj_b     = (const float*)d_in[12];
    const float* n2_g       = (const float*)d_in[13];
    const float* n2_b       = (const float*)d_in[14];
    const float* gate_w     = (const float*)d_in[15];
    const float* gate_b     = (const float*)d_in[16];
    const float* e_w1       = (const float*)d_in[17];
    const float* e_b1       = (const float*)d_in[18];
    const float* e_w2       = (const float*)d_in[19];
    const float* e_b2       = (const float*)d_in[20];
    const float* attn_scale = (const float*)d_in[21];
    const float* mlp_scale  = (const float*)d_in[22];
    const float* norm_g     = (const float*)d_in[23];
    const float* norm_b     = (const float*)d_in[24];
    const float* hc_w       = (const float*)d_in[25];
    const float* hc_b       = (const float*)d_in[26];
    const float* head_w     = (const float*)d_in[27];
    const float* head_b     = (const float*)d_in[28];

    cudaFuncSetAttribute(hypervit_kernel, cudaFuncAttributeMaxDynamicSharedMemorySize,
                         (int)sizeof(SM));
    hypervit_kernel<<<NB, NTHR, sizeof(SM)>>>(
        x, conv_w, conv_b, pe_g, pe_b, cls_token, pos_embed,
        n1_g, n1_b, qkv_w, temp, proj_w, proj_b, n2_g, n2_b,
        gate_w, gate_b, e_w1, e_b1, e_w2, e_b2,
        attn_scale, mlp_scale, norm_g, norm_b, hc_w, hc_b,
        head_w, head_b, (float*)d_out);
}

// round 4
// speedup vs baseline: 2.0534x; 2.0534x over previous
#include <cuda_runtime.h>
#include <math.h>

#define NB 128
#define DD 192
#define DEPTHL 12
#define NHD 3
#define HDIM 64
#define NE 4
#define NT 65
#define NCLS 100
#define DH 384
#define NTHR 384
#define NWARP 12
#define CK 36            // MoE chunk rows (12 warps x 3)
#define OHS 68           // Oh row stride

typedef unsigned long long ull;

struct __align__(16) SM {
    float t[66 * DD];        // residual
    float Y[72 * DD];        // LN output (rows 66-71 zero)
    float S[72 * DD];        // qkv per head; MoE Hc (36*384) aliases
    float Oh[72 * OHS];      // per-head attention out (rows 65-71 zero)
    float2 Wsh[4640];        // weight k-slice [k2][col], padded stride
    float m[72], rs[72];
    float gl[NT * NE];
    float selw[NT * 2];
    float ewt[NE * 72];
    int   seli[NT * 2];
    int   elist[NE * 72];
    int   ecnt[NE];
};

__device__ __forceinline__ ull fma2(ull a, ull b, ull c) {
    ull d;
    asm("fma.rn.f32x2 %0, %1, %2, %3;" : "=l"(d) : "l"(a), "l"(b), "l"(c));
    return d;
}
__device__ __forceinline__ float f2sum(ull v) {
    float lo = __uint_as_float((unsigned)(v & 0xffffffffull));
    float hi = __uint_as_float((unsigned)(v >> 32));
    return lo + hi;
}
__device__ __forceinline__ float gelu_exact(float x) {
    return 0.5f * x * (1.0f + erff(x * 0.70710678118654752f));
}
__device__ __forceinline__ float dot4(float4 a, float4 b) {
    return a.x * b.x + a.y * b.y + a.z * b.z + a.w * b.w;
}

__device__ __forceinline__ void ln_stats(const float* __restrict__ base, int n0, int n1,
                                         float* __restrict__ m, float* __restrict__ rs) {
    int warp = threadIdx.x >> 5, lane = threadIdx.x & 31;
    for (int n = n0 + warp; n < n1; n += NWARP) {
        const float* row = base + n * DD;
        float s = 0.f;
        for (int c = lane; c < DD; c += 32) s += row[c];
#pragma unroll
        for (int o = 16; o; o >>= 1) s += __shfl_xor_sync(0xffffffffu, s, o);
        float mm = s * (1.0f / DD);
        float q = 0.f;
        for (int c = lane; c < DD; c += 32) { float d = row[c] - mm; q += d * d; }
#pragma unroll
        for (int o = 16; o; o >>= 1) q += __shfl_xor_sync(0xffffffffu, q, o);
        if (lane == 0) { m[n] = mm; rs[n] = rsqrtf(q * (1.0f / DD) + 1e-5f); }
    }
}

__global__ void __launch_bounds__(NTHR, 1) hypervit_kernel(
    const float* __restrict__ x, const float* __restrict__ conv_w, const float* __restrict__ conv_b,
    const float* __restrict__ pe_g, const float* __restrict__ pe_b,
    const float* __restrict__ cls_token, const float* __restrict__ pos_embed,
    const float* __restrict__ n1_g, const float* __restrict__ n1_b,
    const float* __restrict__ qkv_w, const float* __restrict__ temp,
    const float* __restrict__ proj_w, const float* __restrict__ proj_b,
    const float* __restrict__ n2_g, const float* __restrict__ n2_b,
    const float* __restrict__ gate_w, const float* __restrict__ gate_b,
    const float* __restrict__ e_w1, const float* __restrict__ e_b1,
    const float* __restrict__ e_w2, const float* __restrict__ e_b2,
    const float* __restrict__ attn_scale, const float* __restrict__ mlp_scale,
    const float* __restrict__ norm_g, const float* __restrict__ norm_b,
    const float* __restrict__ hc_w, const float* __restrict__ hc_b,
    const float* __restrict__ head_w, const float* __restrict__ head_b,
    float* __restrict__ out)
{
    extern __shared__ char smraw[];
    SM* sp = (SM*)smraw;
    const int b = blockIdx.x;
    const int tid = threadIdx.x;
    const int warp = tid >> 5, lane = tid & 31;
    const int rg6 = warp * 6;
    float* t = sp->t;
    float* Y = sp->Y;
    float* S = sp->S;
    float* Oh = sp->Oh;
    float2* Wsh = sp->Wsh;

    // zero pad regions once
    for (int i = tid; i < 6 * DD; i += NTHR) Y[66 * DD + i] = 0.f;
    for (int i = tid; i < 7 * OHS; i += NTHR) Oh[65 * OHS + i] = 0.f;

    // ======================= patch embed =======================
    {
        float* P = Y;  // 64 x 48 (rows 0..15 region)
        for (int i = tid; i < 64 * 48; i += NTHR) {
            int patch = i / 48, f = i % 48;
            int c = f >> 4, pi = (f >> 2) & 3, pj = f & 3;
            int ph = patch >> 3, pw = patch & 7;
            P[i] = x[((b * 3 + c) * 32 + ph * 4 + pi) * 32 + pw * 4 + pj];
        }
        __syncthreads();
        for (int task = tid; task < 64 * DD; task += NTHR) {
            int p = task / DD, c = task % DD;
            const float* w = conv_w + c * 48;
            float acc = conv_b[c];
#pragma unroll
            for (int k = 0; k < 48; k += 4) {
                float4 w4 = *(const float4*)(w + k);
                float4 p4 = *(const float4*)(P + p * 48 + k);
                acc += dot4(p4, w4);
            }
            t[(p + 1) * DD + c] = acc;
        }
        __syncthreads();
        ln_stats(t, 1, 65, sp->m, sp->rs);
        __syncthreads();
        for (int i = tid; i < 64 * DD; i += NTHR) {
            int n = 1 + i / DD, c = i % DD;
            t[n * DD + c] = (t[n * DD + c] - sp->m[n]) * sp->rs[n] * pe_g[c] + pe_b[c]
                            + pos_embed[n * DD + c];
        }
        for (int c = tid; c < DD; c += NTHR) {
            t[c] = cls_token[c] + pos_embed[c];
            t[65 * DD + c] = 0.f;
        }
    }
    __syncthreads();

    // ======================= transformer layers =======================
    for (int l = 0; l < DEPTHL; l++) {
        // ---- LN1 -> Y ----
        ln_stats(t, 0, 65, sp->m, sp->rs);
        __syncthreads();
        for (int i = tid; i < 65 * DD; i += NTHR) {
            int n = i / DD, c = i % DD;
            Y[i] = (t[i] - sp->m[n]) * sp->rs[n] * n1_g[l * DD + c] + n1_b[l * DD + c];
        }
        for (int c = tid; c < DD; c += NTHR) Y[65 * DD + c] = 0.f;
        // sync provided by first staging barrier below

        const float asc = attn_scale[l];

        for (int h = 0; h < NHD; h++) {
            // ===== qkv GEMM: out 72x192 (q|k|v of head h), k=192 =====
            {
                ull acc[36];
#pragma unroll
                for (int i = 0; i < 36; i++) acc[i] = 0ull;
                for (int s = 0; s < 4; s++) {
                    int k0 = s * 24;
                    __syncthreads();
                    for (int i = tid; i < 192 * 24; i += NTHR) {
                        int col = i / 24, kk = i - col * 24;
                        int sec = col >> 6, d = col & 63;
                        const float* wrow = qkv_w + ((size_t)(l * 3 + sec) * DD + h * HDIM + d) * DD;
                        Wsh[kk * 193 + col] = *(const float2*)(wrow + 2 * (k0 + kk));
                    }
                    __syncthreads();
#pragma unroll 2
                    for (int kk = 0; kk < 24; kk++) {
                        ull w[6], y[6];
#pragma unroll
                        for (int j = 0; j < 6; j++) w[j] = *(ull*)&Wsh[kk * 193 + lane + 32 * j];
#pragma unroll
                        for (int r = 0; r < 6; r++) y[r] = *(ull*)(Y + (rg6 + r) * DD + 2 * (k0 + kk));
#pragma unroll
                        for (int j = 0; j < 6; j++)
#pragma unroll
                            for (int r = 0; r < 6; r++)
                                acc[j * 6 + r] = fma2(y[r], w[j], acc[j * 6 + r]);
                    }
                }
#pragma unroll
                for (int j = 0; j < 6; j++)
#pragma unroll
                    for (int r = 0; r < 6; r++)
                        S[(rg6 + r) * DD + lane + 32 * j] = f2sum(acc[j * 6 + r]);
            }
            __syncthreads();

            // ===== banded attention (|i-j|<=3) -> Oh[72][64] =====
            {
                float coef = 0.125f / temp[l * NHD + h];
                for (int i = warp; i < 65; i += NWARP) {
                    int jlo = (i - 3 < 0) ? 0 : i - 3;
                    int jhi = (i + 3 > 64) ? 64 : i + 3;
                    int cnt = jhi - jlo + 1;
                    float2 qv = *(const float2*)(S + i * DD + 2 * lane);
                    float sc[7];
#pragma unroll
                    for (int jj = 0; jj < 7; jj++) {
                        if (jj < cnt) {
                            float2 kv = *(const float2*)(S + (jlo + jj) * DD + 64 + 2 * lane);
                            float p = qv.x * kv.x + qv.y * kv.y;
#pragma unroll
                            for (int o = 16; o; o >>= 1) p += __shfl_xor_sync(0xffffffffu, p, o);
                            sc[jj] = p * coef;
                        }
                    }
                    float mx = sc[0];
#pragma unroll
                    for (int jj = 1; jj < 7; jj++) if (jj < cnt) mx = fmaxf(mx, sc[jj]);
                    float ssum = 0.f;
#pragma unroll
                    for (int jj = 0; jj < 7; jj++) if (jj < cnt) { sc[jj] = expf(sc[jj] - mx); ssum += sc[jj]; }
                    float inv = 1.0f / ssum;
                    float o0 = 0.f, o1 = 0.f;
#pragma unroll
                    for (int jj = 0; jj < 7; jj++) {
                        if (jj < cnt) {
                            float2 vv = *(const float2*)(S + (jlo + jj) * DD + 128 + 2 * lane);
                            o0 += sc[jj] * vv.x;
                            o1 += sc[jj] * vv.y;
                        }
                    }
                    Oh[i * OHS + 2 * lane]     = o0 * inv;
                    Oh[i * OHS + 2 * lane + 1] = o1 * inv;
                }
            }

            // ===== proj partial: t += asc * Oh @ proj_w[:, h*64:(h+1)*64]^T =====
            {
                ull acc[36];
#pragma unroll
                for (int i = 0; i < 36; i++) acc[i] = 0ull;
                for (int s = 0; s < 2; s++) {
                    int k0 = s * 16;
                    __syncthreads();
                    for (int i = tid; i < 192 * 16; i += NTHR) {
                        int col = i / 16, kk = i - col * 16;
                        const float* wrow = proj_w + ((size_t)l * DD + col) * DD + h * HDIM;
                        Wsh[kk * 193 + col] = *(const float2*)(wrow + 2 * (k0 + kk));
                    }
                    __syncthreads();
#pragma unroll 2
                    for (int kk = 0; kk < 16; kk++) {
                        ull w[6], y[6];
#pragma unroll
                        for (int j = 0; j < 6; j++) w[j] = *(ull*)&Wsh[kk * 193 + lane + 32 * j];
#pragma unroll
                        for (int r = 0; r < 6; r++) y[r] = *(ull*)(Oh + (rg6 + r) * OHS + 2 * (k0 + kk));
#pragma unroll
                        for (int j = 0; j < 6; j++)
#pragma unroll
                            for (int r = 0; r < 6; r++)
                                acc[j * 6 + r] = fma2(y[r], w[j], acc[j * 6 + r]);
                    }
                }
#pragma unroll
                for (int r = 0; r < 6; r++) {
                    int row = rg6 + r;
                    if (row < 66) {
#pragma unroll
                        for (int j = 0; j < 6; j++) {
                            int col = lane + 32 * j;
                            float add = f2sum(acc[j * 6 + r]);
                            if (h == 0) add += proj_b[l * DD + col];
                            t[row * DD + col] += asc * add;
                        }
                    }
                }
            }
            __syncthreads();
        }

        // ---- LN2 -> Y ----
        ln_stats(t, 0, 65, sp->m, sp->rs);
        __syncthreads();
        for (int i = tid; i < 65 * DD; i += NTHR) {
            int n = i / DD, c = i % DD;
            Y[i] = (t[i] - sp->m[n]) * sp->rs[n] * n2_g[l * DD + c] + n2_b[l * DD + c];
        }
        for (int c = tid; c < DD; c += NTHR) Y[65 * DD + c] = 0.f;
        __syncthreads();

        // ---- gating ----
        for (int task = tid; task < NT * NE; task += NTHR) {
            int n = task >> 2, e = task & 3;
            const float* gw = gate_w + ((size_t)l * NE + e) * DD;
            float acc = gate_b[l * NE + e];
            for (int c = 0; c < DD; c += 4) {
                float4 y4 = *(const float4*)(Y + n * DD + c);
                float4 w4 = *(const float4*)(gw + c);
                acc += dot4(y4, w4);
            }
            sp->gl[n * NE + e] = acc;
        }
        __syncthreads();
        if (tid < NT) {
            float vv[4] = { sp->gl[tid * 4 + 0], sp->gl[tid * 4 + 1],
                            sp->gl[tid * 4 + 2], sp->gl[tid * 4 + 3] };
            int i0 = 0; float bmax = vv[0];
#pragma unroll
            for (int e = 1; e < 4; e++) if (vv[e] > bmax) { bmax = vv[e]; i0 = e; }
            int i1 = -1; float b2v = -1e30f;
#pragma unroll
            for (int e = 0; e < 4; e++) if (e != i0 && vv[e] > b2v) { b2v = vv[e]; i1 = e; }
            float w1 = expf(b2v - bmax);
            float inv = 1.0f / (1.0f + w1);
            sp->seli[tid * 2 + 0] = i0;
            sp->seli[tid * 2 + 1] = i1;
            sp->selw[tid * 2 + 0] = inv;
            sp->selw[tid * 2 + 1] = w1 * inv;
        }
        __syncthreads();
        if (tid == 0) {
            float msc = mlp_scale[l];
            int cnt[4] = { 0, 0, 0, 0 };
            for (int n = 0; n < NT; n++) {
                for (int sidx = 0; sidx < 2; sidx++) {
                    int e = sp->seli[n * 2 + sidx];
                    sp->elist[e * 72 + cnt[e]] = n;
                    sp->ewt[e * 72 + cnt[e]] = sp->selw[n * 2 + sidx] * msc;
                    cnt[e]++;
                }
            }
            for (int e = 0; e < 4; e++) {
                while (cnt[e] % CK != 0) {
                    sp->elist[e * 72 + cnt[e]] = 65;   // pad: Y row 65 = 0
                    sp->ewt[e * 72 + cnt[e]] = 0.f;
                    cnt[e]++;
                }
                sp->ecnt[e] = cnt[e];
            }
        }
        __syncthreads();

        // ---- expert FFNs (36-row chunks, token-indirect) ----
        float* Hc = S;   // 36 x 384
        for (int e = 0; e < NE; e++) {
            int cnt = sp->ecnt[e];
            int nch = cnt / CK;
            for (int ch = 0; ch < nch; ch++) {
                int base = e * 72 + ch * CK;
                int tok0 = sp->elist[base + warp * 3 + 0];
                int tok1 = sp->elist[base + warp * 3 + 1];
                int tok2 = sp->elist[base + warp * 3 + 2];

                // ===== G1: 36 x 384 = Y[toks] @ w1^T, gelu =====
                {
                    ull acc[36];
#pragma unroll
                    for (int i = 0; i < 36; i++) acc[i] = 0ull;
                    const float* w1b = e_w1 + (size_t)(l * NE + e) * DH * DD;
                    for (int s = 0; s < 8; s++) {
                        int k0 = s * 12;
                        __syncthreads();
                        for (int i = tid; i < 384 * 12; i += NTHR) {
                            int col = i / 12, kk = i - col * 12;
                            Wsh[kk * 385 + col] = *(const float2*)(w1b + (size_t)col * DD + 2 * (k0 + kk));
                        }
                        __syncthreads();
#pragma unroll 2
                        for (int kk = 0; kk < 12; kk++) {
                            ull w[12], y0, y1, y2;
#pragma unroll
                            for (int j = 0; j < 12; j++) w[j] = *(ull*)&Wsh[kk * 385 + lane + 32 * j];
                            y0 = *(ull*)(Y + tok0 * DD + 2 * (k0 + kk));
                            y1 = *(ull*)(Y + tok1 * DD + 2 * (k0 + kk));
                            y2 = *(ull*)(Y + tok2 * DD + 2 * (k0 + kk));
#pragma unroll
                            for (int j = 0; j < 12; j++) {
                                acc[j * 3 + 0] = fma2(y0, w[j], acc[j * 3 + 0]);
                                acc[j * 3 + 1] = fma2(y1, w[j], acc[j * 3 + 1]);
                                acc[j * 3 + 2] = fma2(y2, w[j], acc[j * 3 + 2]);
                            }
                        }
                    }
                    const float* b1 = e_b1 + (size_t)(l * NE + e) * DH;
#pragma unroll
                    for (int j = 0; j < 12; j++) {
                        int col = lane + 32 * j;
                        float bias = b1[col];
                        Hc[(warp * 3 + 0) * DH + col] = gelu_exact(f2sum(acc[j * 3 + 0]) + bias);
                        Hc[(warp * 3 + 1) * DH + col] = gelu_exact(f2sum(acc[j * 3 + 1]) + bias);
                        Hc[(warp * 3 + 2) * DH + col] = gelu_exact(f2sum(acc[j * 3 + 2]) + bias);
                    }
                }

                // ===== G2: 36 x 192 = Hc @ w2^T, scatter += t =====
                {
                    ull acc[18];
#pragma unroll
                    for (int i = 0; i < 18; i++) acc[i] = 0ull;
                    const float* w2b = e_w2 + (size_t)(l * NE + e) * DD * DH;
                    for (int s = 0; s < 8; s++) {
                        int k0 = s * 24;
                        __syncthreads();
                        for (int i = tid; i < 192 * 24; i += NTHR) {
                            int col = i / 24, kk = i - col * 24;
                            Wsh[kk * 193 + col] = *(const float2*)(w2b + (size_t)col * DH + 2 * (k0 + kk));
                        }
                        __syncthreads();
#pragma unroll 2
                        for (int kk = 0; kk < 24; kk++) {
                            ull w[6], y0, y1, y2;
#pragma unroll
                            for (int j = 0; j < 6; j++) w[j] = *(ull*)&Wsh[kk * 193 + lane + 32 * j];
                            y0 = *(ull*)(Hc + (warp * 3 + 0) * DH + 2 * (k0 + kk));
                            y1 = *(ull*)(Hc + (warp * 3 + 1) * DH + 2 * (k0 + kk));
                            y2 = *(ull*)(Hc + (warp * 3 + 2) * DH + 2 * (k0 + kk));
#pragma unroll
                            for (int j = 0; j < 6; j++) {
                                acc[j * 3 + 0] = fma2(y0, w[j], acc[j * 3 + 0]);
                                acc[j * 3 + 1] = fma2(y1, w[j], acc[j * 3 + 1]);
                                acc[j * 3 + 2] = fma2(y2, w[j], acc[j * 3 + 2]);
                            }
                        }
                    }
                    float wt0 = sp->ewt[base + warp * 3 + 0];
                    float wt1 = sp->ewt[base + warp * 3 + 1];
                    float wt2 = sp->ewt[base + warp * 3 + 2];
                    const float* b2 = e_b2 + (size_t)(l * NE + e) * DD;
#pragma unroll
                    for (int j = 0; j < 6; j++) {
                        int col = lane + 32 * j;
                        float bias = b2[col];
                        t[tok0 * DD + col] += wt0 * (f2sum(acc[j * 3 + 0]) + bias);
                        t[tok1 * DD + col] += wt1 * (f2sum(acc[j * 3 + 1]) + bias);
                        t[tok2 * DD + col] += wt2 * (f2sum(acc[j * 3 + 2]) + bias);
                    }
                }
                __syncthreads();
            }
        }
    }

    // ======================= final norm + circulant head =======================
    ln_stats(t, 0, 1, sp->m, sp->rs);
    __syncthreads();
    float* cls = Y;
    for (int c = tid; c < DD; c += NTHR)
        cls[c] = (t[c] - sp->m[0]) * sp->rs[0] * norm_g[c] + norm_b[c];
    __syncthreads();
    float* HH = S;
    for (int ko = tid; ko < 2 * DD; ko += NTHR) {
        int k = ko / 96, o = ko % 96;
        float acc = hc_b[ko];
#pragma unroll
        for (int j = 0; j < 4; j++) {
            const float* w = hc_w + ((size_t)((k - j) & 3) * 96 + o) * 48;
            const float* xv = cls + j * 48;
#pragma unroll
            for (int c = 0; c < 48; c += 4) {
                float4 w4 = *(const float4*)(w + c);
                float4 x4 = *(const float4*)(xv + c);
                acc += dot4(x4, w4);
            }
        }
        HH[ko] = gelu_exact(acc);
    }
    __syncthreads();
    for (int ci = tid; ci < NCLS; ci += NTHR) {
        const float* w = head_w + (size_t)ci * (2 * DD);
        float acc = head_b[ci];
        for (int c = 0; c < 2 * DD; c += 4) {
            float4 w4 = *(const float4*)(w + c);
            float4 h4 = *(const float4*)(HH + c);
            acc += dot4(h4, w4);
        }
        out[b * NCLS + ci] = acc;
    }
}

extern "C" void kernel_launch(void* const* d_in, const int* in_sizes, int n_in,
                              void* d_out, int out_size) {
    (void)in_sizes; (void)n_in; (void)out_size;
    const float* x          = (const float*)d_in[0];
    const float* conv_w     = (const float*)d_in[1];
    const float* conv_b     = (const float*)d_in[2];
    const float* pe_g       = (const float*)d_in[3];
    const float* pe_b       = (const float*)d_in[4];
    const float* cls_token  = (const float*)d_in[5];
    const float* pos_embed  = (const float*)d_in[6];
    const float* n1_g       = (const float*)d_in[7];
    const float* n1_b       = (const float*)d_in[8];
    const float* qkv_w      = (const float*)d_in[9];
    const float* temp       = (const float*)d_in[10];
    const float* proj_w     = (const float*)d_in[11];
    const float* proj_b     = (const float*)d_in[12];
    const float* n2_g       = (const float*)d_in[13];
    const float* n2_b       = (const float*)d_in[14];
    const float* gate_w     = (const float*)d_in[15];
    const float* gate_b     = (const float*)d_in[16];
    const float* e_w1       = (const float*)d_in[17];
    const float* e_b1       = (const float*)d_in[18];
    const float* e_w2       = (const float*)d_in[19];
    const float* e_b2       = (const float*)d_in[20];
    const float* attn_scale = (const float*)d_in[21];
    const float* mlp_scale  = (const float*)d_in[22];
    const float* norm_g     = (const float*)d_in[23];
    const float* norm_b     = (const float*)d_in[24];
    const float* hc_w       = (const float*)d_in[25];
    const float* hc_b       = (const float*)d_in[26];
    const float* head_w     = (const float*)d_in[27];
    const float* head_b     = (const float*)d_in[28];

    cudaFuncSetAttribute(hypervit_kernel, cudaFuncAttributeMaxDynamicSharedMemorySize,
                         (int)sizeof(SM));
    hypervit_kernel<<<NB, NTHR, sizeof(SM)>>>(
        x, conv_w, conv_b, pe_g, pe_b, cls_token, pos_embed,
        n1_g, n1_b, qkv_w, temp, proj_w, proj_b, n2_g, n2_b,
        gate_w, gate_b, e_w1, e_b1, e_w2, e_b2,
        attn_scale, mlp_scale, norm_g, norm_b, hc_w, hc_b,
        head_w, head_b, (float*)d_out);
}